// round 16
// baseline (speedup 1.0000x reference)
#include <cuda_runtime.h>
#include <math.h>

#define Kc 16
#define Mc 32
#define PK (Mc * Kc * Kc)        /* 8192  */
#define PTOT (3 * PK + Kc)       /* 24592 */
#define TBL 2048
#define SM_FLOATS (PK + Kc + TBL)   /* P, w, exp-table */
#define SMEM_BYTES (SM_FLOATS * 4)  /* 41024 */
#define THREADS 256

typedef unsigned long long u64;

// Precomputed params, transposed layout [i][j][k] (k fastest):
//   [0,PK)     P = -a^2            (a = s/sigma, s = sqrt(log2e/2))
//   [PK,2PK)   Q = -2ab            (b = -s*mu/sigma)
//   [2PK,3PK)  R = c - b^2         (c = (logW - log sigma - 0.5log2pi)*log2e)
//   [3PK,+K)   w = softmax(wk0_logits)
// t = (P*x + Q)*x + R == c - (a*x+b)^2, entry = 2^t.
// For k >= 10 (pair ids 5,6,7) P,Q,R are pre-scaled by 2048 so t arrives as
// u = 2048*t, feeding the table path directly.
__device__ __align__(16) float g_P[PTOT];

// Q and R in the constant bank (exactly 64KB): warp-uniform LDC.128 keeps
// this traffic off the LSU. P stays in smem.
__constant__ __align__(16) float c_Q[PK];
__constant__ __align__(16) float c_R[PK];

__global__ void prep_kernel(const float* __restrict__ wk0,
                            const float* __restrict__ W,
                            const float* __restrict__ mu,
                            const float* __restrict__ ps) {
    int idx = blockIdx.x * blockDim.x + threadIdx.x;
    if (idx >= PK) return;
    int i = idx >> 8;
    int k = (idx >> 4) & 15;
    int j = idx & 15;

    // log_softmax over axis=1 (the k index) of W_logits[i, :, j]
    int base = i * 256 + j;
    float m = -1e30f;
#pragma unroll
    for (int kk = 0; kk < Kc; kk++) m = fmaxf(m, W[base + kk * 16]);
    float ssum = 0.f;
#pragma unroll
    for (int kk = 0; kk < Kc; kk++) ssum += expf(W[base + kk * 16] - m);
    float logW = W[idx] - m - logf(ssum);

    float p = ps[idx];
    float sigma = (p > 20.f) ? p : log1pf(expf(p));   // softplus
    float inv = 1.f / sigma;
    float log_sigma = logf(sigma);

    const float LOG2E = 1.4426950408889634f;
    const float HALF_LOG_2PI = 0.9189385332046727f;
    const float S = 0.84932180028801907f;  // sqrt(LOG2E/2)

    float a_ = S * inv;
    float b_ = -S * mu[idx] * inv;
    float c_ = (logW - log_sigma - HALF_LOG_2PI) * LOG2E;

    float Pv = -a_ * a_;
    float Qv = -2.f * a_ * b_;
    float Rv = c_ - b_ * b_;

    // Table-path pairs (k >= 10): pre-scale so t = 2048 * log2(entry).
    if (k >= 10) { Pv *= 2048.f; Qv *= 2048.f; Rv *= 2048.f; }

    int o = i * 256 + j * 16 + k;          // transposed [i][j][k]
    g_P[o]          = Pv;
    g_P[PK + o]     = Qv;
    g_P[2 * PK + o] = Rv;

    if (idx < Kc) {
        float mw = -1e30f;
#pragma unroll
        for (int kk = 0; kk < Kc; kk++) mw = fmaxf(mw, wk0[kk]);
        float sw = 0.f;
#pragma unroll
        for (int kk = 0; kk < Kc; kk++) sw += expf(wk0[kk] - mw);
        g_P[3 * PK + idx] = expf(wk0[idx] - mw) / sw;
    }
}

__device__ __forceinline__ float ex2_approx(float t) {
    float r;
    asm("ex2.approx.ftz.f32 %0, %1;" : "=f"(r) : "f"(t));
    return r;
}
__device__ __forceinline__ u64 pack2(float lo, float hi) {
    u64 r; asm("mov.b64 %0, {%1, %2};" : "=l"(r) : "f"(lo), "f"(hi)); return r;
}
__device__ __forceinline__ void unpack2(u64 v, float& lo, float& hi) {
    asm("mov.b64 {%0, %1}, %2;" : "=f"(lo), "=f"(hi) : "l"(v));
}
__device__ __forceinline__ u64 fma2(u64 a, u64 b, u64 c) {
    u64 d; asm("fma.rn.f32x2 %0, %1, %2, %3;" : "=l"(d) : "l"(a), "l"(b), "l"(c)); return d;
}
__device__ __forceinline__ u64 add2(u64 a, u64 b) {
    u64 d; asm("add.rn.f32x2 %0, %1, %2;" : "=l"(d) : "l"(a), "l"(b)); return d;
}

// MUFU path: 2^t per packed pair.
__device__ __forceinline__ u64 exp2_mufu_pair(u64 t) {
    float a, b; unpack2(t, a, b);
    return pack2(ex2_approx(a), ex2_approx(b));
}

// Table path: input u = 2048*t (pre-scaled via P,Q,R).
// m = round(u) via magic add; bits = 0x4B400000 + m; idx = bits & 2047;
// val_bits = T'[idx] + (bits << 12), where T'[idx] = bits(2^(idx/2048))
//            - (idx << 12)  (idx contamination pre-subtracted; the magic's
//            contribution (0x4B400000 << 12) wraps to 0 mod 2^32).
// Clamp keeps the exponent field >= 1 (deep underflow -> ~1e-38 ~ 0).
__device__ __forceinline__ u64 exp2_table_pair(u64 u, const int* __restrict__ Ti,
                                               u64 MAGIC2, int CLAMPI) {
    u64 rr = add2(u, MAGIC2);
    float rl, rh; unpack2(rr, rl, rh);
    int bl = max(__float_as_int(rl), CLAMPI);
    int bh = max(__float_as_int(rh), CLAMPI);
    int vl = Ti[bl & 2047] + (bl << 12);
    int vh = Ti[bh & 2047] + (bh << 12);
    return pack2(__int_as_float(vl), __int_as_float(vh));
}

__global__ void __launch_bounds__(THREADS, 2)
ttg_main(const float* __restrict__ X, float* __restrict__ out, int N) {
    extern __shared__ float sm[];
    int* Ti = (int*)(sm + PK + Kc);
    {
        const float4* src = (const float4*)g_P;        // P slab only
        float4* dst = (float4*)sm;
        for (int t = threadIdx.x; t < PK / 4; t += blockDim.x) dst[t] = src[t];
        if (threadIdx.x < Kc) sm[PK + threadIdx.x] = g_P[3 * PK + threadIdx.x];
        // exp table: T'[idx] = bits(2^(idx/2048)) - (idx << 12)
        for (int t = threadIdx.x; t < TBL; t += blockDim.x)
            Ti[t] = __float_as_int(exp2f((float)t * (1.0f / 2048.0f))) - (t << 12);
    }
    __syncthreads();

    int n = blockIdx.x * blockDim.x + threadIdx.x;
    if (n >= N) return;

    const u64 MAGIC2 = pack2(12582912.f, 12582912.f);
    const int CLAMPI = 0x4B3C1000;   // 0x4B400000 - 2048*126 (exp field >= 1)

    // v held as 8 packed pairs (k0..k15)
    u64 v2[8];
#pragma unroll
    for (int h = 0; h < 8; h++) v2[h] = pack2(sm[PK + 2 * h], sm[PK + 2 * h + 1]);

    const ulonglong2* s2 = (const ulonglong2*)sm;      // P
    const ulonglong2* q2 = (const ulonglong2*)c_Q;     // Q in constant bank
    const ulonglong2* r2 = (const ulonglong2*)c_R;     // R in constant bank
    const float* Xrow = X + (size_t)n * Mc;

    float xcur = Xrow[0];

#pragma unroll 1
    for (int i = 0; i < Mc; i++) {
        float xnext = Xrow[(i + 1) & 31];          // prefetch (wraps harmlessly)
        u64 x2 = pack2(xcur, xcur);

        u64 vn2[8];
#pragma unroll
        for (int h = 0; h < 8; h++) vn2[h] = 0ull;

        int ib = i * 64;  // 16B-unit index of row block i
#pragma unroll
        for (int jh = 0; jh < 8; jh++) {
            float va, vb; unpack2(v2[jh], va, vb);
#pragma unroll
            for (int jj = 0; jj < 2; jj++) {
                float vjs = jj ? vb : va;
                u64 vj2 = pack2(vjs, vjs);
                int j = 2 * jh + jj;
                int jb = ib + j * 4;
#pragma unroll
                for (int q = 0; q < 4; q++) {
                    ulonglong2 Pq = s2[jb + q];
                    ulonglong2 Qq = q2[jb + q];
                    ulonglong2 Rq = r2[jb + q];
                    u64 t0 = fma2(fma2(Pq.x, x2, Qq.x), x2, Rq.x);
                    u64 t1 = fma2(fma2(Pq.y, x2, Qq.y), x2, Rq.y);
                    // Pair ids 2q / 2q+1: ids >= 5 (k >= 10) take the table
                    // path (t pre-scaled x2048); ids 0-4 take MUFU.
                    // 3/8 table balances MUFU(567K) / FMA(553K) / ALU(539K).
                    u64 r0 = (2 * q >= 5)
                           ? exp2_table_pair(t0, Ti, MAGIC2, CLAMPI)
                           : exp2_mufu_pair(t0);
                    u64 r1 = (2 * q + 1 >= 5)
                           ? exp2_table_pair(t1, Ti, MAGIC2, CLAMPI)
                           : exp2_mufu_pair(t1);
                    vn2[2 * q]     = fma2(r0, vj2, vn2[2 * q]);
                    vn2[2 * q + 1] = fma2(r1, vj2, vn2[2 * q + 1]);
                }
            }
        }
#pragma unroll
        for (int h = 0; h < 8; h++) v2[h] = vn2[h];
        xcur = xnext;
    }

    float s = 0.f;
#pragma unroll
    for (int h = 0; h < 8; h++) {
        float a, b; unpack2(v2[h], a, b);
        s += a + b;
    }
    out[n] = logf(s + 2.2204460492503131e-16f);
}

extern "C" void kernel_launch(void* const* d_in, const int* in_sizes, int n_in,
                              void* d_out, int out_size) {
    const float* X   = (const float*)d_in[0];
    const float* wk0 = (const float*)d_in[1];
    const float* W   = (const float*)d_in[2];
    const float* mu  = (const float*)d_in[3];
    const float* ps  = (const float*)d_in[4];
    float* out = (float*)d_out;
    int N = out_size;

    cudaFuncSetAttribute((const void*)ttg_main,
                         cudaFuncAttributeMaxDynamicSharedMemorySize, SMEM_BYTES);

    prep_kernel<<<(PK + 255) / 256, 256>>>(wk0, W, mu, ps);

    // Copy Q and R slabs of g_P into the constant bank: D2D memcpy nodes,
    // graph-capturable, no allocation.
    void* cqp = nullptr;
    void* crp = nullptr;
    void* gpp = nullptr;
    cudaGetSymbolAddress(&cqp, c_Q);
    cudaGetSymbolAddress(&crp, c_R);
    cudaGetSymbolAddress(&gpp, g_P);
    cudaMemcpyAsync(cqp, (const char*)gpp + (size_t)PK * sizeof(float),
                    (size_t)PK * sizeof(float), cudaMemcpyDeviceToDevice);
    cudaMemcpyAsync(crp, (const char*)gpp + (size_t)2 * PK * sizeof(float),
                    (size_t)PK * sizeof(float), cudaMemcpyDeviceToDevice);

    ttg_main<<<(N + THREADS - 1) / THREADS, THREADS, SMEM_BYTES>>>(X, out, N);
}

// round 17
// speedup vs baseline: 1.3371x; 1.3371x over previous
#include <cuda_runtime.h>
#include <math.h>

#define Kc 16
#define Mc 32
#define PK (Mc * Kc * Kc)        /* 8192  */
#define PTOT (3 * PK + Kc)       /* 24592 */
#define SM_FLOATS (PK + Kc)      /* P and w in smem */
#define SMEM_BYTES (SM_FLOATS * 4)
#define THREADS 256

typedef unsigned long long u64;

// Precomputed params, transposed layout [i][j][k] (k fastest):
//   [0,PK)     P = -a^2            (a = s/sigma, s = sqrt(log2e/2))
//   [PK,2PK)   Q = -2ab            (b = -s*mu/sigma)
//   [2PK,3PK)  R = c - b^2         (c = (logW - log(sigma) - 0.5*log(2pi))*log2e)
//   [3PK,+K)   w = softmax(wk0_logits)
// so t = (P*x + Q)*x + R  ==  c - (a*x+b)^2  and entry = 2^t.
__device__ __align__(16) float g_P[PTOT];

// Q and R live in the constant bank (exactly 64KB): warp-uniform LDC.128
// (~8 cyc/op) keeps this traffic off the LSU; P stays in smem. Halved smem
// per CTA -> 3 CTAs/SM.
__constant__ __align__(16) float c_Q[PK];
__constant__ __align__(16) float c_R[PK];

__global__ void prep_kernel(const float* __restrict__ wk0,
                            const float* __restrict__ W,
                            const float* __restrict__ mu,
                            const float* __restrict__ ps) {
    int idx = blockIdx.x * blockDim.x + threadIdx.x;
    if (idx >= PK) return;
    int i = idx >> 8;
    int k = (idx >> 4) & 15;
    int j = idx & 15;

    // log_softmax over axis=1 (the k index) of W_logits[i, :, j]
    int base = i * 256 + j;
    float m = -1e30f;
#pragma unroll
    for (int kk = 0; kk < Kc; kk++) m = fmaxf(m, W[base + kk * 16]);
    float ssum = 0.f;
#pragma unroll
    for (int kk = 0; kk < Kc; kk++) ssum += expf(W[base + kk * 16] - m);
    float logW = W[idx] - m - logf(ssum);

    float p = ps[idx];
    float sigma = (p > 20.f) ? p : log1pf(expf(p));   // softplus
    float inv = 1.f / sigma;
    float log_sigma = logf(sigma);

    const float LOG2E = 1.4426950408889634f;
    const float HALF_LOG_2PI = 0.9189385332046727f;
    const float S = 0.84932180028801907f;  // sqrt(LOG2E/2)

    float a_ = S * inv;
    float b_ = -S * mu[idx] * inv;
    float c_ = (logW - log_sigma - HALF_LOG_2PI) * LOG2E;

    int o = i * 256 + j * 16 + k;          // transposed [i][j][k]
    g_P[o]          = -a_ * a_;
    g_P[PK + o]     = -2.f * a_ * b_;
    g_P[2 * PK + o] = c_ - b_ * b_;

    if (idx < Kc) {
        float mw = -1e30f;
#pragma unroll
        for (int kk = 0; kk < Kc; kk++) mw = fmaxf(mw, wk0[kk]);
        float sw = 0.f;
#pragma unroll
        for (int kk = 0; kk < Kc; kk++) sw += expf(wk0[kk] - mw);
        g_P[3 * PK + idx] = expf(wk0[idx] - mw) / sw;
    }
}

__device__ __forceinline__ float ex2_approx(float t) {
    float r;
    asm("ex2.approx.ftz.f32 %0, %1;" : "=f"(r) : "f"(t));
    return r;
}
__device__ __forceinline__ u64 pack2(float lo, float hi) {
    u64 r; asm("mov.b64 %0, {%1, %2};" : "=l"(r) : "f"(lo), "f"(hi)); return r;
}
__device__ __forceinline__ void unpack2(u64 v, float& lo, float& hi) {
    asm("mov.b64 {%0, %1}, %2;" : "=f"(lo), "=f"(hi) : "l"(v));
}
__device__ __forceinline__ u64 fma2(u64 a, u64 b, u64 c) {
    u64 d; asm("fma.rn.f32x2 %0, %1, %2, %3;" : "=l"(d) : "l"(a), "l"(b), "l"(c)); return d;
}
__device__ __forceinline__ u64 add2(u64 a, u64 b) {
    u64 d; asm("add.rn.f32x2 %0, %1, %2;" : "=l"(d) : "l"(a), "l"(b)); return d;
}

// 2^t for a packed pair. poly==false -> MUFU ex2; poly==true -> FMA-pipe
// path: round-to-int trick + deg-2 Horner (rel-centered minimax on [-0.5,0.5],
// max rel err ~1.9e-3 -- zero-mean, washes out in the path averaging) +
// integer exponent splice on the ALU pipe.
// t is always negative here; only the low side needs clamping.
__device__ __forceinline__ u64 exp2pair(u64 t, bool poly,
                                        u64 MAGIC2, u64 NMAGIC2, u64 M1_2,
                                        u64 C1, u64 C2, u64 C0) {
    if (!poly) {
        float a, b; unpack2(t, a, b);
        return pack2(ex2_approx(a), ex2_approx(b));
    } else {
        u64 rr = add2(t, MAGIC2);            // 12582912 + round(t), exact
        u64 fi = add2(rr, NMAGIC2);          // round(t) as float pair
        u64 f  = fma2(fi, M1_2, t);          // f = t - round(t), in [-0.5, 0.5]
        u64 pp = fma2(C2, f, C1);
        pp = fma2(pp, f, C0);                // ~2^f (deg-2, rel-centered)
        float rl, rh; unpack2(rr, rl, rh);
        int il = __float_as_int(rl);
        int ih = __float_as_int(rh);
        il = max(il, 0x4B3FFF83);            // clamp i >= -125
        ih = max(ih, 0x4B3FFF83);
        float pl, ph; unpack2(pp, pl, ph);
        float el = __int_as_float((int)(__float_as_int(pl) + ((unsigned)il << 23)));
        float eh = __int_as_float((int)(__float_as_int(ph) + ((unsigned)ih << 23)));
        return pack2(el, eh);
    }
}

__global__ void __launch_bounds__(THREADS, 3)
ttg_main(const float* __restrict__ X, float* __restrict__ out, int N) {
    extern __shared__ float sm[];
    {
        const float4* src = (const float4*)g_P;        // P slab only
        float4* dst = (float4*)sm;
        for (int t = threadIdx.x; t < PK / 4; t += blockDim.x) dst[t] = src[t];
        if (threadIdx.x < Kc) sm[PK + threadIdx.x] = g_P[3 * PK + threadIdx.x];
    }
    __syncthreads();

    int n = blockIdx.x * blockDim.x + threadIdx.x;
    if (n >= N) return;

    const u64 MAGIC2  = pack2(12582912.f, 12582912.f);
    const u64 NMAGIC2 = pack2(-12582912.f, -12582912.f);
    const u64 M1_2    = pack2(-1.f, -1.f);
    // deg-2 rel-centered minimax coefficients for 2^f on [-0.5,0.5]
    const u64 C0      = pack2(0.99942290f, 0.99942290f);
    const u64 C1      = pack2(0.70324820f, 0.70324820f);
    const u64 C2      = pack2(0.24250570f, 0.24250570f);

    // v held as 8 packed pairs (k0..k15)
    u64 v2[8];
#pragma unroll
    for (int h = 0; h < 8; h++) v2[h] = pack2(sm[PK + 2 * h], sm[PK + 2 * h + 1]);

    const ulonglong2* s2 = (const ulonglong2*)sm;      // P
    const ulonglong2* q2 = (const ulonglong2*)c_Q;     // Q in constant bank
    const ulonglong2* r2 = (const ulonglong2*)c_R;     // R in constant bank
    const float* Xrow = X + (size_t)n * Mc;

    float xcur = Xrow[0];

#pragma unroll 1
    for (int i = 0; i < Mc; i++) {
        float xnext = Xrow[(i + 1) & 31];          // prefetch (wraps harmlessly)
        u64 x2 = pack2(xcur, xcur);

        u64 vn2[8];
#pragma unroll
        for (int h = 0; h < 8; h++) vn2[h] = 0ull;

        int ib = i * 64;  // 16B-unit index of row block i
#pragma unroll
        for (int jh = 0; jh < 8; jh++) {
            float va, vb; unpack2(v2[jh], va, vb);
#pragma unroll
            for (int jj = 0; jj < 2; jj++) {
                float vjs = jj ? vb : va;
                u64 vj2 = pack2(vjs, vjs);
                int j = 2 * jh + jj;
                int jb = ib + j * 4;
#pragma unroll
                for (int q = 0; q < 4; q++) {
                    ulonglong2 Pq = s2[jb + q];
                    ulonglong2 Qq = q2[jb + q];
                    ulonglong2 Rq = r2[jb + q];
                    u64 t0 = fma2(fma2(Pq.x, x2, Qq.x), x2, Rq.x);
                    u64 t1 = fma2(fma2(Pq.y, x2, Qq.y), x2, Rq.y);
                    // Pairs 6,7 take the 13-cyc deg-2 poly path (p = 0.25):
                    // FMA = 510K + 737K*0.25 = 694K, MUFU = 907K*0.75 = 680K.
                    u64 r0 = exp2pair(t0, (2 * q)     >= 6, MAGIC2, NMAGIC2, M1_2, C1, C2, C0);
                    u64 r1 = exp2pair(t1, (2 * q + 1) >= 6, MAGIC2, NMAGIC2, M1_2, C1, C2, C0);
                    vn2[2 * q]     = fma2(r0, vj2, vn2[2 * q]);
                    vn2[2 * q + 1] = fma2(r1, vj2, vn2[2 * q + 1]);
                }
            }
        }
#pragma unroll
        for (int h = 0; h < 8; h++) v2[h] = vn2[h];
        xcur = xnext;
    }

    float s = 0.f;
#pragma unroll
    for (int h = 0; h < 8; h++) {
        float a, b; unpack2(v2[h], a, b);
        s += a + b;
    }
    out[n] = logf(s + 2.2204460492503131e-16f);
}

extern "C" void kernel_launch(void* const* d_in, const int* in_sizes, int n_in,
                              void* d_out, int out_size) {
    const float* X   = (const float*)d_in[0];
    const float* wk0 = (const float*)d_in[1];
    const float* W   = (const float*)d_in[2];
    const float* mu  = (const float*)d_in[3];
    const float* ps  = (const float*)d_in[4];
    float* out = (float*)d_out;
    int N = out_size;

    cudaFuncSetAttribute((const void*)ttg_main,
                         cudaFuncAttributeMaxDynamicSharedMemorySize, SMEM_BYTES);

    prep_kernel<<<(PK + 255) / 256, 256>>>(wk0, W, mu, ps);

    // Copy Q and R slabs of g_P into the constant bank: D2D memcpy nodes,
    // graph-capturable, no allocation.
    void* cqp = nullptr;
    void* crp = nullptr;
    void* gpp = nullptr;
    cudaGetSymbolAddress(&cqp, c_Q);
    cudaGetSymbolAddress(&crp, c_R);
    cudaGetSymbolAddress(&gpp, g_P);
    cudaMemcpyAsync(cqp, (const char*)gpp + (size_t)PK * sizeof(float),
                    (size_t)PK * sizeof(float), cudaMemcpyDeviceToDevice);
    cudaMemcpyAsync(crp, (const char*)gpp + (size_t)2 * PK * sizeof(float),
                    (size_t)PK * sizeof(float), cudaMemcpyDeviceToDevice);

    ttg_main<<<(N + THREADS - 1) / THREADS, THREADS, SMEM_BYTES>>>(X, out, N);
}